// round 13
// baseline (speedup 1.0000x reference)
#include <cuda_runtime.h>
#include <cuda_fp16.h>
#include <cstdint>

// ---------------- problem constants ----------------
#define SEQ   4096
#define HD    64
#define NH    4
#define BM    64           // s rows per CTA
#define BN    64           // t cols per iteration
#define NTH   256
#define ITERS (SEQ/BN)     // 64

// smem row stride for Q/K/V tiles: 136 halves = 272B (68 words ≡ 4 mod 32)
#define SQH  136
#define SQHB (SQH*2)

// smem byte offsets
#define QS_OFF 0
#define KS_OFF (QS_OFF + BM*SQHB)         // 17408
#define VS_OFF (KS_OFF + 2*BN*SQHB)       // 52224
#define SMEM_BYTES (VS_OFF + 2*BN*SQHB)   // 87040
#define TBUF_BYTES (BN*SQHB)              // 17408

// ---------------- device scratch ----------------
__device__ unsigned g_mask_bits[SEQ * (SEQ / 32)];     // 2 MB packed mask
__device__ float    g_v1sum[NH * HD];                  // sum_t V[1,h,t,d]
__device__ __half   g_kh[NH * SEQ * 128];              // [h][t][k0|k1] fp16
__device__ __half   g_vh[NH * SEQ * 128];              // [h][t][v0|v1] fp16

// ---------------- helpers ----------------
__device__ __forceinline__ float ex2_fast(float x) {
    float y; asm("ex2.approx.f32 %0, %1;" : "=f"(y) : "f"(x)); return y;
}
__device__ __forceinline__ float rcp_fast(float x) {
    float y; asm("rcp.approx.f32 %0, %1;" : "=f"(y) : "f"(x)); return y;
}
__device__ __forceinline__ float sigp(float d) {
    const float C = -0.18033688011111652f;   // -0.125 * log2(e)
    return rcp_fast(1.0f + ex2_fast(d * C));
}
__device__ __forceinline__ uint32_t f22u(float a, float b) {
    __half2 h = __floats2half2_rn(a, b);
    return *(uint32_t*)&h;
}
__device__ __forceinline__ uint32_t smem_u32(const void* p) {
    uint32_t a;
    asm("{ .reg .u64 t; cvta.to.shared.u64 t, %1; cvt.u32.u64 %0, t; }" : "=r"(a) : "l"(p));
    return a;
}

#define CP_ASYNC16(dst, src) \
    asm volatile("cp.async.cg.shared.global [%0], [%1], 16;" :: "r"(dst), "l"(src) : "memory")
#define CP_COMMIT() asm volatile("cp.async.commit_group;" ::: "memory")
#define CP_WAIT0()  asm volatile("cp.async.wait_group 0;" ::: "memory")

#define LDSM_X4(r, addr) asm volatile( \
    "ldmatrix.sync.aligned.m8n8.x4.shared.b16 {%0,%1,%2,%3}, [%4];" \
    : "=r"((r)[0]), "=r"((r)[1]), "=r"((r)[2]), "=r"((r)[3]) : "r"(addr))

#define LDSM_X4T(r, addr) asm volatile( \
    "ldmatrix.sync.aligned.m8n8.x4.trans.shared.b16 {%0,%1,%2,%3}, [%4];" \
    : "=r"((r)[0]), "=r"((r)[1]), "=r"((r)[2]), "=r"((r)[3]) : "r"(addr))

#define MMA16816(d, a, b0, b1) asm volatile( \
    "mma.sync.aligned.m16n8k16.row.col.f32.f16.f16.f32 " \
    "{%0,%1,%2,%3}, {%4,%5,%6,%7}, {%8,%9}, {%0,%1,%2,%3};" \
    : "+f"((d)[0]), "+f"((d)[1]), "+f"((d)[2]), "+f"((d)[3]) \
    : "r"((a)[0]), "r"((a)[1]), "r"((a)[2]), "r"((a)[3]), "r"(b0), "r"(b1))

// ---------------- prologue kernels ----------------
__global__ void pack_mask_kernel(const int* __restrict__ mask) {
    int w = blockIdx.x * blockDim.x + threadIdx.x;      // 0 .. SEQ*128-1
    const int4* src = (const int4*)(mask + (size_t)w * 32);
    unsigned bits = 0;
    #pragma unroll
    for (int g = 0; g < 8; g++) {
        int4 v = src[g];
        bits |= (v.x != 0 ? 1u : 0u) << (g * 4 + 0);
        bits |= (v.y != 0 ? 1u : 0u) << (g * 4 + 1);
        bits |= (v.z != 0 ? 1u : 0u) << (g * 4 + 2);
        bits |= (v.w != 0 ? 1u : 0u) << (g * 4 + 3);
    }
    g_mask_bits[w] = bits;
}

__global__ void v1sum_kernel(const float* __restrict__ v) {
    __shared__ float red[256];
    int h = blockIdx.x;
    int d = threadIdx.x & 63;
    int part = threadIdx.x >> 6;
    float s = 0.f;
    for (int t = part; t < SEQ; t += 4)
        s += v[(((size_t)NH + h) * SEQ + t) * HD + d];   // b=1
    red[threadIdx.x] = s;
    __syncthreads();
    if (part == 0)
        g_v1sum[h * HD + d] = red[d] + red[64 + d] + red[128 + d] + red[192 + d];
}

// convert K,V fp32 -> packed fp16 [h][t][b0|b1]
__global__ void convert_kv_kernel(const float* __restrict__ k,
                                  const float* __restrict__ v) {
    int i = blockIdx.x * blockDim.x + threadIdx.x;   // 0 .. NH*SEQ*16-1
    int c   = i & 15;          // 16B chunk within 256B row
    int row = i >> 4;          // h*SEQ + t
    int b   = c >> 3;
    int d0  = (c & 7) * 8;
    size_t g = ((size_t)b * NH * SEQ + row) * HD + d0;
    float4 a0 = *(const float4*)(k + g);
    float4 a1 = *(const float4*)(k + g + 4);
    uint4 o;
    o.x = f22u(a0.x, a0.y); o.y = f22u(a0.z, a0.w);
    o.z = f22u(a1.x, a1.y); o.w = f22u(a1.z, a1.w);
    *(uint4*)(g_kh + (size_t)row * 128 + c * 8) = o;
    float4 b0v = *(const float4*)(v + g);
    float4 b1v = *(const float4*)(v + g + 4);
    uint4 p;
    p.x = f22u(b0v.x, b0v.y); p.y = f22u(b0v.z, b0v.w);
    p.z = f22u(b1v.x, b1v.y); p.w = f22u(b1v.z, b1v.w);
    *(uint4*)(g_vh + (size_t)row * 128 + c * 8) = p;
}

// ---------------- main kernel ----------------
__global__ __launch_bounds__(NTH, 2)
void sdpa_mma_kernel(const float* __restrict__ q,
                     float* __restrict__ out,
                     float* __restrict__ attn)
{
    extern __shared__ char sm[];
    const uint32_t smb = smem_u32(sm);

    const int h   = blockIdx.y;
    const int s0  = blockIdx.x * BM;
    const int tid = threadIdx.x;
    const int w    = tid >> 5;
    const int lane = tid & 31;
    const int gr  = lane >> 2;     // 0..7
    const int ct  = lane & 3;      // 0..3
    const int mg  = w >> 1;        // m-group: 16 rows (0..3)
    const int ng  = w & 1;         // N-half of MMA2 / output batch

    const size_t hseq = (size_t)h * SEQ;

    // ---- cp.async staging identity (K,V tiles: 64 rows x 256B each) ----
    const int srow0 = tid >> 4;           // 0..15
    const int sc16  = tid & 15;           // 16B chunk col
    const uint32_t dstb = (uint32_t)(srow0 * SQHB + sc16 * 16);
    const size_t   srcb = ((size_t)srow0) * 128 + sc16 * 8;

    // ---- stage Q (once): A = [q0 | -q1], fp16 ----
    {
        const int pr0 = tid >> 5;      // 0..7
        const int pc4 = tid & 31;
        const int pb  = pc4 >> 4;
        const int pd4 = pc4 & 15;
        const size_t bh = ((size_t)pb * NH + h) * SEQ;
        const float sgn = pb ? -1.f : 1.f;
        #pragma unroll
        for (int j = 0; j < 8; j++) {
            int row = pr0 + 8 * j;
            float4 val = *(const float4*)(q + (bh + s0 + row) * HD + pd4 * 4);
            uint2 o;
            o.x = f22u(sgn * val.x, sgn * val.y);
            o.y = f22u(sgn * val.z, sgn * val.w);
            *(uint2*)(sm + QS_OFF + row * SQHB + pc4 * 8) = o;
        }
    }

    // ---- issue cp.async for tile 0 ----
    {
        const __half* kp = g_kh + hseq * 128;
        const __half* vp = g_vh + hseq * 128;
        #pragma unroll
        for (int j = 0; j < 4; j++) {
            uint32_t d = dstb + j * 16 * SQHB;
            size_t   s = srcb + (size_t)j * 16 * 128;
            CP_ASYNC16(smb + KS_OFF + d, kp + s);
            CP_ASYNC16(smb + VS_OFF + d, vp + s);
        }
        CP_COMMIT();
    }

    // ---- ldmatrix lane-address bases ----
    const uint32_t qa = smb + QS_OFF + (mg * 16 + (lane & 15)) * SQHB
                      + (lane >> 4) * 16;
    const uint32_t kbofs = ((lane & 7) + (lane >> 4) * 8) * SQHB
                         + ((lane >> 3) & 1) * 16;
    // V: trans; this warp reads its 64-col half (ng*64 halves = ng*128 bytes)
    const uint32_t vbofs = ((lane & 7) + ((lane >> 3) & 1) * 8) * SQHB
                         + (lane >> 4) * 16 + ng * 128;

    // ---- persistent O accumulators: warp tile 16 rows x 64 cols ----
    float oc[8][4];
    #pragma unroll
    for (int nt = 0; nt < 8; nt++)
        #pragma unroll
        for (int u = 0; u < 4; u++) oc[nt][u] = 0.f;

    const int r0 = s0 + mg * 16 + gr;     // this thread's attn rows r0, r0+8
    // ng=0 stores p into attn[b=0]; ng=1 stores 1-p into attn[b=1]
    float* ab = attn + ((size_t)ng * NH * SEQ + hseq + r0) * SEQ + 2 * ct;

    __syncthreads();   // Qs visible (paired with first in-loop barrier semantics)

    for (int it = 0; it < ITERS; ++it) {
        const int t0  = it * BN;
        const uint32_t buf = (it & 1) * TBUF_BYTES;

        CP_WAIT0();
        __syncthreads();

        // ---- issue cp.async for tile it+1 into other buffer ----
        if (it + 1 < ITERS) {
            const uint32_t nbuf = ((it + 1) & 1) * TBUF_BYTES;
            const __half* kp = g_kh + (hseq + t0 + BN) * 128;
            const __half* vp = g_vh + (hseq + t0 + BN) * 128;
            #pragma unroll
            for (int j = 0; j < 4; j++) {
                uint32_t d = dstb + j * 16 * SQHB;
                size_t   s = srcb + (size_t)j * 16 * 128;
                CP_ASYNC16(smb + KS_OFF + nbuf + d, kp + s);
                CP_ASYNC16(smb + VS_OFF + nbuf + d, vp + s);
            }
            CP_COMMIT();
        }

        // ---- MMA1: Delta[16][64] = [q0|-q1] * [k0|k1]^T (dup per pair) ----
        float sc[8][4];
        #pragma unroll
        for (int nt = 0; nt < 8; nt++)
            #pragma unroll
            for (int u = 0; u < 4; u++) sc[nt][u] = 0.f;

        const uint32_t kb = smb + KS_OFF + buf + kbofs;
        #pragma unroll
        for (int kk = 0; kk < 8; kk++) {
            uint32_t a[4];
            LDSM_X4(a, qa + kk * 32);
            #pragma unroll
            for (int nb = 0; nb < 4; nb++) {
                uint32_t b[4];
                LDSM_X4(b, kb + nb * 16 * SQHB + kk * 32);
                MMA16816(sc[2*nb],     a, b[0], b[1]);
                MMA16816(sc[2*nb + 1], a, b[2], b[3]);
            }
        }

        // ---- sigmoid + mask (in place) ----
        {
            unsigned long long mw0 =
                *(const unsigned long long*)(g_mask_bits + (size_t)r0 * 128 + it * 2);
            unsigned long long mw1 =
                *(const unsigned long long*)(g_mask_bits + (size_t)(r0 + 8) * 128 + it * 2);
            #pragma unroll
            for (int nt = 0; nt < 8; nt++) {
                int bp = nt * 8 + 2 * ct;
                sc[nt][0] = ((mw0 >> bp) & 1)       ? 0.5f : sigp(sc[nt][0]);
                sc[nt][1] = ((mw0 >> (bp + 1)) & 1) ? 0.5f : sigp(sc[nt][1]);
                sc[nt][2] = ((mw1 >> bp) & 1)       ? 0.5f : sigp(sc[nt][2]);
                sc[nt][3] = ((mw1 >> (bp + 1)) & 1) ? 0.5f : sigp(sc[nt][3]);
            }
        }

        // ---- convert P to fp16 A-fragments (register passing) ----
        uint32_t pa[4][4];
        #pragma unroll
        for (int kt = 0; kt < 4; kt++) {
            pa[kt][0] = f22u(sc[2*kt][0],     sc[2*kt][1]);
            pa[kt][1] = f22u(sc[2*kt][2],     sc[2*kt][3]);
            pa[kt][2] = f22u(sc[2*kt + 1][0], sc[2*kt + 1][1]);
            pa[kt][3] = f22u(sc[2*kt + 1][2], sc[2*kt + 1][3]);
        }

        // ---- MMA2: O[16][64] += P * V_ng ----
        const uint32_t vb = smb + VS_OFF + buf + vbofs;
        #pragma unroll
        for (int kt = 0; kt < 4; kt++) {
            #pragma unroll
            for (int nb = 0; nb < 4; nb++) {
                uint32_t b[4];
                LDSM_X4T(b, vb + kt * 16 * SQHB + nb * 32);
                MMA16816(oc[2*nb],     pa[kt], b[0], b[1]);
                MMA16816(oc[2*nb + 1], pa[kt], b[2], b[3]);
            }
        }

        // ---- attn stores straight from registers (evict-first) ----
        // ng=0 warp: attn0 = p ; ng=1 warp: attn1 = 1-p
        {
            float* a0 = ab + t0;
            if (ng == 0) {
                #pragma unroll
                for (int nt = 0; nt < 8; nt++) {
                    int c = nt * 8;
                    __stcs((float2*)(a0 + c),         make_float2(sc[nt][0], sc[nt][1]));
                    __stcs((float2*)(a0 + c + 8*SEQ), make_float2(sc[nt][2], sc[nt][3]));
                }
            } else {
                #pragma unroll
                for (int nt = 0; nt < 8; nt++) {
                    int c = nt * 8;
                    __stcs((float2*)(a0 + c),
                           make_float2(1.f - sc[nt][0], 1.f - sc[nt][1]));
                    __stcs((float2*)(a0 + c + 8*SEQ),
                           make_float2(1.f - sc[nt][2], 1.f - sc[nt][3]));
                }
            }
        }
    }

    // ---- final out write: ng=0 -> b0 = acc ; ng=1 -> b1 = v1sum - acc ----
    const float* vs = g_v1sum + h * HD;
    #pragma unroll
    for (int nt = 0; nt < 8; nt++) {
        int d = nt * 8 + 2 * ct;
        float* c = oc[nt];
        float2 w0, w1;
        if (ng == 0) {
            w0 = make_float2(c[0], c[1]);
            w1 = make_float2(c[2], c[3]);
        } else {
            w0 = make_float2(vs[d] - c[0], vs[d + 1] - c[1]);
            w1 = make_float2(vs[d] - c[2], vs[d + 1] - c[3]);
        }
        size_t ob = (((size_t)ng * NH + h) * SEQ + r0) * HD + d;
        *(float2*)(out + ob)          = w0;
        *(float2*)(out + ob + 8 * HD) = w1;
    }
}

// ---------------- launcher ----------------
extern "C" void kernel_launch(void* const* d_in, const int* in_sizes, int n_in,
                              void* d_out, int out_size)
{
    const float* q    = (const float*)d_in[0];
    const float* k    = (const float*)d_in[1];
    const float* v    = (const float*)d_in[2];
    const int*   mask = (const int*)  d_in[3];

    float* out  = (float*)d_out;
    float* attn = out + (size_t)2 * NH * SEQ * HD;

    pack_mask_kernel<<<SEQ * 128 / 256, 256>>>(mask);
    v1sum_kernel<<<NH, 256>>>(v);
    convert_kv_kernel<<<NH * SEQ * 16 / 256, 256>>>(k, v);

    cudaFuncSetAttribute(sdpa_mma_kernel,
                         cudaFuncAttributeMaxDynamicSharedMemorySize, SMEM_BYTES);
    dim3 grid(SEQ / BM, NH);
    sdpa_mma_kernel<<<grid, NTH, SMEM_BYTES>>>(q, out, attn);
}

// round 14
// speedup vs baseline: 1.3041x; 1.3041x over previous
#include <cuda_runtime.h>
#include <cuda_fp16.h>
#include <cstdint>

// ---------------- problem constants ----------------
#define SEQ   4096
#define HD    64
#define NH    4
#define BM    64           // s rows per CTA
#define BN    64           // t cols per iteration
#define NTH   256
#define ITERS (SEQ/BN)     // 64

// smem strides: rows are 272B (136 halves; 68 words ≡ 4 mod 32 banks)
#define SQH 136            // Qs/Ks/Vs row stride (halves)
#define SPH 72             // Ps row stride (halves)

// smem byte offsets
#define QS_OFF 0
#define KS_OFF (QS_OFF + BM*SQH*2)        // 17408
#define VS_OFF (KS_OFF + 2*BN*SQH*2)      // 52224
#define PS_OFF (VS_OFF + 2*BN*SQH*2)      // 87040
#define SMEM_BYTES (PS_OFF + BM*SPH*2)    // 96256
#define TBUF_BYTES (BN*SQH*2)             // 17408

// ---------------- device scratch ----------------
__device__ unsigned g_mask_bits[SEQ * (SEQ / 32)];     // 2 MB packed mask
__device__ float    g_v1sum[NH * HD];                  // sum_t V[1,h,t,d]
__device__ __half   g_kh[NH * SEQ * 128];              // [h][t][k0|k1] fp16
__device__ __half   g_vh[NH * SEQ * 128];              // [h][t][v0|v1] fp16

// ---------------- helpers ----------------
__device__ __forceinline__ float tanh_fast(float x) {
    float y; asm("tanh.approx.f32 %0, %1;" : "=f"(y) : "f"(x)); return y;
}
// sigmoid(0.125*d) = 0.5 + 0.5*tanh(0.0625*d) ; single MUFU op
__device__ __forceinline__ float sigp(float d) {
    return fmaf(tanh_fast(d * 0.0625f), 0.5f, 0.5f);
}
__device__ __forceinline__ uint32_t f22u(float a, float b) {
    __half2 h = __floats2half2_rn(a, b);
    return *(uint32_t*)&h;
}
__device__ __forceinline__ uint32_t smem_u32(const void* p) {
    uint32_t a;
    asm("{ .reg .u64 t; cvta.to.shared.u64 t, %1; cvt.u32.u64 %0, t; }" : "=r"(a) : "l"(p));
    return a;
}

#define CP_ASYNC16(dst, src) \
    asm volatile("cp.async.cg.shared.global [%0], [%1], 16;" :: "r"(dst), "l"(src) : "memory")
#define CP_COMMIT() asm volatile("cp.async.commit_group;" ::: "memory")
#define CP_WAIT0()  asm volatile("cp.async.wait_group 0;" ::: "memory")

#define LDSM_X4(r, addr) asm volatile( \
    "ldmatrix.sync.aligned.m8n8.x4.shared.b16 {%0,%1,%2,%3}, [%4];" \
    : "=r"((r)[0]), "=r"((r)[1]), "=r"((r)[2]), "=r"((r)[3]) : "r"(addr))

#define LDSM_X4T(r, addr) asm volatile( \
    "ldmatrix.sync.aligned.m8n8.x4.trans.shared.b16 {%0,%1,%2,%3}, [%4];" \
    : "=r"((r)[0]), "=r"((r)[1]), "=r"((r)[2]), "=r"((r)[3]) : "r"(addr))

#define MMA16816(d, a, b0, b1) asm volatile( \
    "mma.sync.aligned.m16n8k16.row.col.f32.f16.f16.f32 " \
    "{%0,%1,%2,%3}, {%4,%5,%6,%7}, {%8,%9}, {%0,%1,%2,%3};" \
    : "+f"((d)[0]), "+f"((d)[1]), "+f"((d)[2]), "+f"((d)[3]) \
    : "r"((a)[0]), "r"((a)[1]), "r"((a)[2]), "r"((a)[3]), "r"(b0), "r"(b1))

// ---------------- prologue kernels ----------------
__global__ void pack_mask_kernel(const int* __restrict__ mask) {
    int w = blockIdx.x * blockDim.x + threadIdx.x;      // 0 .. SEQ*128-1
    const int4* src = (const int4*)(mask + (size_t)w * 32);
    unsigned bits = 0;
    #pragma unroll
    for (int g = 0; g < 8; g++) {
        int4 v = src[g];
        bits |= (v.x != 0 ? 1u : 0u) << (g * 4 + 0);
        bits |= (v.y != 0 ? 1u : 0u) << (g * 4 + 1);
        bits |= (v.z != 0 ? 1u : 0u) << (g * 4 + 2);
        bits |= (v.w != 0 ? 1u : 0u) << (g * 4 + 3);
    }
    g_mask_bits[w] = bits;
}

__global__ void v1sum_kernel(const float* __restrict__ v) {
    __shared__ float red[256];
    int h = blockIdx.x;
    int d = threadIdx.x & 63;
    int part = threadIdx.x >> 6;
    float s = 0.f;
    for (int t = part; t < SEQ; t += 4)
        s += v[(((size_t)NH + h) * SEQ + t) * HD + d];   // b=1
    red[threadIdx.x] = s;
    __syncthreads();
    if (part == 0)
        g_v1sum[h * HD + d] = red[d] + red[64 + d] + red[128 + d] + red[192 + d];
}

// convert K,V fp32 -> packed fp16 [h][t][b0|b1]
__global__ void convert_kv_kernel(const float* __restrict__ k,
                                  const float* __restrict__ v) {
    int i = blockIdx.x * blockDim.x + threadIdx.x;   // 0 .. NH*SEQ*16-1
    int c   = i & 15;          // 16B chunk within 256B row
    int row = i >> 4;          // h*SEQ + t
    int b   = c >> 3;
    int d0  = (c & 7) * 8;
    size_t g = ((size_t)b * NH * SEQ + row) * HD + d0;
    float4 a0 = *(const float4*)(k + g);
    float4 a1 = *(const float4*)(k + g + 4);
    uint4 o;
    o.x = f22u(a0.x, a0.y); o.y = f22u(a0.z, a0.w);
    o.z = f22u(a1.x, a1.y); o.w = f22u(a1.z, a1.w);
    *(uint4*)(g_kh + (size_t)row * 128 + c * 8) = o;
    float4 b0v = *(const float4*)(v + g);
    float4 b1v = *(const float4*)(v + g + 4);
    uint4 p;
    p.x = f22u(b0v.x, b0v.y); p.y = f22u(b0v.z, b0v.w);
    p.z = f22u(b1v.x, b1v.y); p.w = f22u(b1v.z, b1v.w);
    *(uint4*)(g_vh + (size_t)row * 128 + c * 8) = p;
}

// ---------------- main kernel ----------------
__global__ __launch_bounds__(NTH, 2)
void sdpa_mma_kernel(const float* __restrict__ q,
                     float* __restrict__ out,
                     float* __restrict__ attn)
{
    extern __shared__ char sm[];
    const uint32_t smb = smem_u32(sm);

    const int h   = blockIdx.y;
    const int s0  = blockIdx.x * BM;
    const int tid = threadIdx.x;
    const int w    = tid >> 5;
    const int lane = tid & 31;
    const int gr  = lane >> 2;     // group id (0..7)
    const int ct  = lane & 3;      // thread-in-group
    const int wm  = w & 1;         // warp m-group (32 rows) 0..1
    const int wn  = w >> 1;        // warp n-group 0..3

    const size_t hseq = (size_t)h * SEQ;

    // ---- cp.async staging identity: 4 chunks per tile per thread ----
    const int srow0 = tid >> 4;           // 0..15
    const int sc16  = tid & 15;           // chunk col
    const uint32_t dstb = (uint32_t)(srow0 * (SQH*2) + sc16 * 16);
    const size_t   srcb = ((size_t)srow0) * 128 + sc16 * 8;

    // ---- stage Q (once): A = [q0 | -q1], fp16 ----
    {
        const int pr0 = tid >> 5;      // 0..7
        const int pc4 = tid & 31;
        const int pb  = pc4 >> 4;
        const int pd4 = pc4 & 15;
        const size_t bh = ((size_t)pb * NH + h) * SEQ;
        const float sgn = pb ? -1.f : 1.f;
        #pragma unroll
        for (int j = 0; j < 8; j++) {
            int row = pr0 + 8 * j;
            float4 val = *(const float4*)(q + (bh + s0 + row) * HD + pd4 * 4);
            uint2 o;
            o.x = f22u(sgn * val.x, sgn * val.y);
            o.y = f22u(sgn * val.z, sgn * val.w);
            *(uint2*)(sm + QS_OFF + row * (SQH*2) + pc4 * 8) = o;
        }
    }

    // ---- issue cp.async for tile 0 ----
    {
        const __half* kp = g_kh + hseq * 128;
        const __half* vp = g_vh + hseq * 128;
        #pragma unroll
        for (int j = 0; j < 4; j++) {
            uint32_t d = dstb + j * 16 * (SQH*2);
            size_t   s = srcb + (size_t)j * 16 * 128;
            CP_ASYNC16(smb + KS_OFF + d, kp + s);
            CP_ASYNC16(smb + VS_OFF + d, vp + s);
        }
        CP_COMMIT();
    }

    // ---- ldmatrix lane-address bases (byte offsets) ----
    const uint32_t qa = smb + QS_OFF + (wm*32 + (lane & 15)) * (SQH*2) + (lane >> 4) * 16;
    const uint32_t kbofs = (uint32_t)((wn*16 + (lane & 7) + (lane >> 4) * 8) * (SQH*2)
                        + ((lane >> 3) & 1) * 16);
    const uint32_t pa = smb + PS_OFF + (wm*32 + (lane & 15)) * (SPH*2) + (lane >> 4) * 16;
    const uint32_t vbrow = ((lane & 7) + ((lane >> 3) & 1) * 8) * (SQH*2);
    const uint32_t vbcol = (wn*32 + (lane >> 4) * 8) * 2;

    // ---- persistent O accumulators: warp tile 32 rows x 32 cols ----
    float oc[2][4][4];
    #pragma unroll
    for (int mt = 0; mt < 2; mt++)
        #pragma unroll
        for (int nt = 0; nt < 4; nt++)
            #pragma unroll
            for (int u = 0; u < 4; u++) oc[mt][nt][u] = 0.f;

    float* attn1 = attn + (size_t)NH * SEQ * SEQ;

    for (int it = 0; it < ITERS; ++it) {
        const int t0  = it * BN;
        const uint32_t buf = (it & 1) * TBUF_BYTES;

        CP_WAIT0();
        __syncthreads();

        // ---- issue cp.async for tile it+1 into other buffer ----
        if (it + 1 < ITERS) {
            const uint32_t nbuf = ((it + 1) & 1) * TBUF_BYTES;
            const __half* kp = g_kh + (hseq + t0 + BN) * 128;
            const __half* vp = g_vh + (hseq + t0 + BN) * 128;
            #pragma unroll
            for (int j = 0; j < 4; j++) {
                uint32_t d = dstb + j * 16 * (SQH*2);
                size_t   s = srcb + (size_t)j * 16 * 128;
                CP_ASYNC16(smb + KS_OFF + nbuf + d, kp + s);
                CP_ASYNC16(smb + VS_OFF + nbuf + d, vp + s);
            }
            CP_COMMIT();
        }

        // ---- MMA1: Delta[64][64] = [q0|-q1] * [k0|k1]^T ; warp tile 32x16 ----
        float sc[2][2][4];
        #pragma unroll
        for (int mt = 0; mt < 2; mt++)
            #pragma unroll
            for (int nt = 0; nt < 2; nt++)
                #pragma unroll
                for (int u = 0; u < 4; u++) sc[mt][nt][u] = 0.f;

        const uint32_t kb = smb + KS_OFF + buf + kbofs;
        #pragma unroll
        for (int kk = 0; kk < 8; kk++) {
            uint32_t a0[4], a1[4], b[4];
            LDSM_X4(a0, qa + kk * 32);
            LDSM_X4(a1, qa + kk * 32 + 16 * (SQH*2));
            LDSM_X4(b,  kb + kk * 32);
            MMA16816(sc[0][0], a0, b[0], b[1]);
            MMA16816(sc[0][1], a0, b[2], b[3]);
            MMA16816(sc[1][0], a1, b[0], b[1]);
            MMA16816(sc[1][1], a1, b[2], b[3]);
        }

        // ---- epilogue: mask (zero delta) + tanh-sigmoid ; stage P (fp16) ----
        #pragma unroll
        for (int mt = 0; mt < 2; mt++) {
            #pragma unroll
            for (int u = 0; u < 2; u++) {
                int row = wm*32 + mt*16 + gr + 8*u;
                unsigned mw = g_mask_bits[(size_t)(s0 + row) * 128 + it * 2 + (wn >> 1)];
                #pragma unroll
                for (int nt = 0; nt < 2; nt++) {
                    int bitb = (wn & 1) * 16 + nt * 8 + 2 * ct;
                    // masked -> delta = 0 -> tanh(0)=0 -> p = 0.5 exactly
                    float x0 = ((mw >> bitb) & 1)       ? 0.f : sc[mt][nt][2*u + 0];
                    float x1 = ((mw >> (bitb + 1)) & 1) ? 0.f : sc[mt][nt][2*u + 1];
                    float p0 = sigp(x0);
                    float p1 = sigp(x1);
                    *(uint32_t*)(sm + PS_OFF + row * (SPH*2)
                                 + (wn*16 + nt*8 + 2*ct) * 2) = f22u(p0, p1);
                }
            }
        }
        __syncthreads();

        // ---- MMA2: O[64][128] += P0 * [V0|V1] ; warp tile 32x32 ----
        #pragma unroll
        for (int kk = 0; kk < 4; kk++) {
            uint32_t a0[4], a1[4], bA[4], bB[4];
            LDSM_X4(a0, pa + kk * 32);
            LDSM_X4(a1, pa + kk * 32 + 16 * (SPH*2));
            uint32_t vaddr = smb + VS_OFF + buf + vbrow + vbcol + (uint32_t)kk * 16 * (SQH*2);
            LDSM_X4T(bA, vaddr);
            LDSM_X4T(bB, vaddr + 32);
            MMA16816(oc[0][0], a0, bA[0], bA[1]);
            MMA16816(oc[0][1], a0, bA[2], bA[3]);
            MMA16816(oc[0][2], a0, bB[0], bB[1]);
            MMA16816(oc[0][3], a0, bB[2], bB[3]);
            MMA16816(oc[1][0], a1, bA[0], bA[1]);
            MMA16816(oc[1][1], a1, bA[2], bA[3]);
            MMA16816(oc[1][2], a1, bB[0], bB[1]);
            MMA16816(oc[1][3], a1, bB[2], bB[3]);
        }

        // ---- attn stores (after MMA2; overlap with next-iter wait) ----
        {
            const int g  = tid & 7;            // 8-half group
            const int rr = tid >> 3;           // 0..31
            #pragma unroll
            for (int j = 0; j < 2; j++) {
                int row = j * 32 + rr;
                uint4 u4 = *(uint4*)(sm + PS_OFF + row * (SPH*2) + g * 16);
                float2 f0 = __half22float2(*(__half2*)&u4.x);
                float2 f1 = __half22float2(*(__half2*)&u4.y);
                float2 f2 = __half22float2(*(__half2*)&u4.z);
                float2 f3 = __half22float2(*(__half2*)&u4.w);
                size_t ab = (hseq + s0 + row) * SEQ + t0 + g * 8;
                __stcs((float4*)(attn + ab),     make_float4(f0.x, f0.y, f1.x, f1.y));
                __stcs((float4*)(attn + ab + 4), make_float4(f2.x, f2.y, f3.x, f3.y));
                __stcs((float4*)(attn1 + ab),
                       make_float4(1.f - f0.x, 1.f - f0.y, 1.f - f1.x, 1.f - f1.y));
                __stcs((float4*)(attn1 + ab + 4),
                       make_float4(1.f - f2.x, 1.f - f2.y, 1.f - f3.x, 1.f - f3.y));
            }
        }
    }

    // ---- final out write: wn 0,1 -> b0 = acc ; wn 2,3 -> b1 = v1sum - acc ----
    const float* vs = g_v1sum + h * HD;
    const int b = wn >> 1;
    #pragma unroll
    for (int mt = 0; mt < 2; mt++) {
        int row = s0 + wm*32 + mt*16 + gr;
        #pragma unroll
        for (int nt = 0; nt < 4; nt++) {
            int n0 = wn*32 + nt*8 + 2*ct;
            int d  = n0 & 63;
            float* c = oc[mt][nt];
            float2 w0, w1;
            if (b == 0) {
                w0 = make_float2(c[0], c[1]);
                w1 = make_float2(c[2], c[3]);
            } else {
                w0 = make_float2(vs[d] - c[0], vs[d + 1] - c[1]);
                w1 = make_float2(vs[d] - c[2], vs[d + 1] - c[3]);
            }
            size_t ob = (((size_t)b * NH + h) * SEQ + row) * HD + d;
            *(float2*)(out + ob)          = w0;
            *(float2*)(out + ob + 8 * HD) = w1;
        }
    }
}

// ---------------- launcher ----------------
extern "C" void kernel_launch(void* const* d_in, const int* in_sizes, int n_in,
                              void* d_out, int out_size)
{
    const float* q    = (const float*)d_in[0];
    const float* k    = (const float*)d_in[1];
    const float* v    = (const float*)d_in[2];
    const int*   mask = (const int*)  d_in[3];

    float* out  = (float*)d_out;
    float* attn = out + (size_t)2 * NH * SEQ * HD;

    pack_mask_kernel<<<SEQ * 128 / 256, 256>>>(mask);
    v1sum_kernel<<<NH, 256>>>(v);
    convert_kv_kernel<<<NH * SEQ * 16 / 256, 256>>>(k, v);

    cudaFuncSetAttribute(sdpa_mma_kernel,
                         cudaFuncAttributeMaxDynamicSharedMemorySize, SMEM_BYTES);
    dim3 grid(SEQ / BM, NH);
    sdpa_mma_kernel<<<grid, NTH, SMEM_BYTES>>>(q, out, attn);
}

// round 15
// speedup vs baseline: 1.6392x; 1.2570x over previous
#include <cuda_runtime.h>
#include <cuda_fp16.h>
#include <cstdint>

// ---------------- problem constants ----------------
#define SEQ   4096
#define HD    64
#define NH    4
#define BM    64           // s rows per CTA
#define BN    64           // t cols per iteration
#define NTH   256
#define ITERS (SEQ/BN)     // 64

// smem strides: rows are 272B (136 halves; 68 words ≡ 4 mod 32 banks)
#define SQH 136            // Qs/Ks/Vs row stride (halves)
#define SPH 72             // Ps row stride (halves)

// smem byte offsets
#define QS_OFF 0
#define KS_OFF (QS_OFF + BM*SQH*2)        // 17408
#define VS_OFF (KS_OFF + 2*BN*SQH*2)      // 52224
#define PS_OFF (VS_OFF + 2*BN*SQH*2)      // 87040
#define SMEM_BYTES (PS_OFF + BM*SPH*2)    // 96256
#define TBUF_BYTES (BN*SQH*2)             // 17408

// ---------------- device scratch ----------------
__device__ unsigned g_mask_bits[SEQ * (SEQ / 32)];     // 2 MB packed mask
__device__ float    g_v1sum[NH * HD];                  // sum_t V[1,h,t,d]
__device__ __half   g_kh[NH * SEQ * 128];              // [h][t][k0|k1] fp16
__device__ __half   g_vh[NH * SEQ * 128];              // [h][t][v0|v1] fp16

// ---------------- helpers ----------------
__device__ __forceinline__ float tanh_fast(float x) {
    float y; asm("tanh.approx.f32 %0, %1;" : "=f"(y) : "f"(x)); return y;
}
// Q pre-scaled by 0.0625: p = 0.5 + 0.5*tanh(delta_scaled)
__device__ __forceinline__ float sigp(float d) {
    return fmaf(tanh_fast(d), 0.5f, 0.5f);
}
__device__ __forceinline__ uint32_t f22u(float a, float b) {
    __half2 h = __floats2half2_rn(a, b);
    return *(uint32_t*)&h;
}
__device__ __forceinline__ uint32_t smem_u32(const void* p) {
    uint32_t a;
    asm("{ .reg .u64 t; cvta.to.shared.u64 t, %1; cvt.u32.u64 %0, t; }" : "=r"(a) : "l"(p));
    return a;
}

#define CP_ASYNC16(dst, src) \
    asm volatile("cp.async.cg.shared.global [%0], [%1], 16;" :: "r"(dst), "l"(src) : "memory")
#define CP_COMMIT() asm volatile("cp.async.commit_group;" ::: "memory")
#define CP_WAIT0()  asm volatile("cp.async.wait_group 0;" ::: "memory")
#define BAR_SYNC(id) asm volatile("bar.sync %0, 128;" :: "r"(id) : "memory")

#define LDSM_X4(r, addr) asm volatile( \
    "ldmatrix.sync.aligned.m8n8.x4.shared.b16 {%0,%1,%2,%3}, [%4];" \
    : "=r"((r)[0]), "=r"((r)[1]), "=r"((r)[2]), "=r"((r)[3]) : "r"(addr))

#define LDSM_X4T(r, addr) asm volatile( \
    "ldmatrix.sync.aligned.m8n8.x4.trans.shared.b16 {%0,%1,%2,%3}, [%4];" \
    : "=r"((r)[0]), "=r"((r)[1]), "=r"((r)[2]), "=r"((r)[3]) : "r"(addr))

#define MMA16816(d, a, b0, b1) asm volatile( \
    "mma.sync.aligned.m16n8k16.row.col.f32.f16.f16.f32 " \
    "{%0,%1,%2,%3}, {%4,%5,%6,%7}, {%8,%9}, {%0,%1,%2,%3};" \
    : "+f"((d)[0]), "+f"((d)[1]), "+f"((d)[2]), "+f"((d)[3]) \
    : "r"((a)[0]), "r"((a)[1]), "r"((a)[2]), "r"((a)[3]), "r"(b0), "r"(b1))

// ---------------- fused prologue kernel ----------------
// blocks [0,2048): pack mask ; [2048,3072): convert K/V ; [3072,3076): v1sum
__global__ void prologue_kernel(const int* __restrict__ mask,
                                const float* __restrict__ k,
                                const float* __restrict__ v) {
    const int bx = blockIdx.x;
    const int tid = threadIdx.x;
    if (bx < 2048) {
        int w = bx * 256 + tid;                     // 0 .. SEQ*128-1
        const int4* src = (const int4*)(mask + (size_t)w * 32);
        unsigned bits = 0;
        #pragma unroll
        for (int g = 0; g < 8; g++) {
            int4 m4 = src[g];
            bits |= (m4.x != 0 ? 1u : 0u) << (g * 4 + 0);
            bits |= (m4.y != 0 ? 1u : 0u) << (g * 4 + 1);
            bits |= (m4.z != 0 ? 1u : 0u) << (g * 4 + 2);
            bits |= (m4.w != 0 ? 1u : 0u) << (g * 4 + 3);
        }
        g_mask_bits[w] = bits;
    } else if (bx < 3072) {
        int i = (bx - 2048) * 256 + tid;            // 0 .. NH*SEQ*16-1
        int c   = i & 15;
        int row = i >> 4;
        int b   = c >> 3;
        int d0  = (c & 7) * 8;
        size_t g = ((size_t)b * NH * SEQ + row) * HD + d0;
        float4 a0 = *(const float4*)(k + g);
        float4 a1 = *(const float4*)(k + g + 4);
        uint4 o;
        o.x = f22u(a0.x, a0.y); o.y = f22u(a0.z, a0.w);
        o.z = f22u(a1.x, a1.y); o.w = f22u(a1.z, a1.w);
        *(uint4*)(g_kh + (size_t)row * 128 + c * 8) = o;
        float4 b0v = *(const float4*)(v + g);
        float4 b1v = *(const float4*)(v + g + 4);
        uint4 p;
        p.x = f22u(b0v.x, b0v.y); p.y = f22u(b0v.z, b0v.w);
        p.z = f22u(b1v.x, b1v.y); p.w = f22u(b1v.z, b1v.w);
        *(uint4*)(g_vh + (size_t)row * 128 + c * 8) = p;
    } else {
        __shared__ float red[256];
        int h = bx - 3072;
        int d = tid & 63;
        int part = tid >> 6;
        float s = 0.f;
        for (int t = part; t < SEQ; t += 4)
            s += v[(((size_t)NH + h) * SEQ + t) * HD + d];   // b=1
        red[tid] = s;
        __syncthreads();
        if (part == 0)
            g_v1sum[h * HD + d] = red[d] + red[64 + d] + red[128 + d] + red[192 + d];
    }
}

// ---------------- main kernel ----------------
__global__ __launch_bounds__(NTH, 2)
void sdpa_mma_kernel(const float* __restrict__ q,
                     float* __restrict__ out,
                     float* __restrict__ attn)
{
    extern __shared__ char sm[];
    const uint32_t smb = smem_u32(sm);

    const int h   = blockIdx.y;
    const int s0  = blockIdx.x * BM;
    const int tid = threadIdx.x;
    const int w    = tid >> 5;
    const int lane = tid & 31;
    const int gr  = lane >> 2;     // group id (0..7)
    const int ct  = lane & 3;      // thread-in-group
    const int wm  = w & 1;         // warp m-group (32 rows) 0..1
    const int wn  = w >> 1;        // warp n-group 0..3

    const size_t hseq = (size_t)h * SEQ;

    // ---- cp.async staging identity: 4 chunks per tile per thread ----
    const int srow0 = tid >> 4;           // 0..15
    const int sc16  = tid & 15;           // chunk col
    const uint32_t dstb = (uint32_t)(srow0 * (SQH*2) + sc16 * 16);
    const size_t   srcb = ((size_t)srow0) * 128 + sc16 * 8;

    // ---- stage Q (once): A = [q0 | -q1] * 0.0625, fp16 (scale exact) ----
    {
        const int pr0 = tid >> 5;      // 0..7
        const int pc4 = tid & 31;
        const int pb  = pc4 >> 4;
        const int pd4 = pc4 & 15;
        const size_t bh = ((size_t)pb * NH + h) * SEQ;
        const float sgn = pb ? -0.0625f : 0.0625f;
        #pragma unroll
        for (int j = 0; j < 8; j++) {
            int row = pr0 + 8 * j;
            float4 val = *(const float4*)(q + (bh + s0 + row) * HD + pd4 * 4);
            uint2 o;
            o.x = f22u(sgn * val.x, sgn * val.y);
            o.y = f22u(sgn * val.z, sgn * val.w);
            *(uint2*)(sm + QS_OFF + row * (SQH*2) + pc4 * 8) = o;
        }
    }

    // ---- issue cp.async for tile 0 ----
    {
        const __half* kp = g_kh + hseq * 128;
        const __half* vp = g_vh + hseq * 128;
        #pragma unroll
        for (int j = 0; j < 4; j++) {
            uint32_t d = dstb + j * 16 * (SQH*2);
            size_t   s = srcb + (size_t)j * 16 * 128;
            CP_ASYNC16(smb + KS_OFF + d, kp + s);
            CP_ASYNC16(smb + VS_OFF + d, vp + s);
        }
        CP_COMMIT();
    }

    // ---- ldmatrix lane-address bases (byte offsets) ----
    const uint32_t qa = smb + QS_OFF + (wm*32 + (lane & 15)) * (SQH*2) + (lane >> 4) * 16;
    const uint32_t kbofs = (uint32_t)((wn*16 + (lane & 7) + (lane >> 4) * 8) * (SQH*2)
                        + ((lane >> 3) & 1) * 16);
    const uint32_t pa = smb + PS_OFF + (wm*32 + (lane & 15)) * (SPH*2) + (lane >> 4) * 16;
    const uint32_t vbrow = ((lane & 7) + ((lane >> 3) & 1) * 8) * (SQH*2);
    const uint32_t vbcol = (wn*32 + (lane >> 4) * 8) * 2;

    // ---- persistent O accumulators: warp tile 32 rows x 32 cols ----
    float oc[2][4][4];
    #pragma unroll
    for (int mt = 0; mt < 2; mt++)
        #pragma unroll
        for (int nt = 0; nt < 4; nt++)
            #pragma unroll
            for (int u = 0; u < 4; u++) oc[mt][nt][u] = 0.f;

    float* attn1 = attn + (size_t)NH * SEQ * SEQ;
    // epilogue row/col identity
    const int erow0 = s0 + wm*32 + gr;               // + mt*16 + 8u
    const int ecol0 = wn*16 + 2*ct;                  // + nt*8 ; + t0

    for (int it = 0; it < ITERS; ++it) {
        const int t0  = it * BN;
        const uint32_t buf = (it & 1) * TBUF_BYTES;

        CP_WAIT0();
        __syncthreads();

        // ---- issue cp.async for tile it+1 into other buffer ----
        if (it + 1 < ITERS) {
            const uint32_t nbuf = ((it + 1) & 1) * TBUF_BYTES;
            const __half* kp = g_kh + (hseq + t0 + BN) * 128;
            const __half* vp = g_vh + (hseq + t0 + BN) * 128;
            #pragma unroll
            for (int j = 0; j < 4; j++) {
                uint32_t d = dstb + j * 16 * (SQH*2);
                size_t   s = srcb + (size_t)j * 16 * 128;
                CP_ASYNC16(smb + KS_OFF + nbuf + d, kp + s);
                CP_ASYNC16(smb + VS_OFF + nbuf + d, vp + s);
            }
            CP_COMMIT();
        }

        // ---- prefetch mask words (hide L2 latency behind MMA1) ----
        unsigned mw[2][2];
        #pragma unroll
        for (int mt = 0; mt < 2; mt++)
            #pragma unroll
            for (int u = 0; u < 2; u++)
                mw[mt][u] = g_mask_bits[(size_t)(erow0 + mt*16 + 8*u) * 128
                                        + it * 2 + (wn >> 1)];

        // ---- MMA1: Delta[64][64] ; warp tile 32x16 ----
        float sc[2][2][4];
        #pragma unroll
        for (int mt = 0; mt < 2; mt++)
            #pragma unroll
            for (int nt = 0; nt < 2; nt++)
                #pragma unroll
                for (int u = 0; u < 4; u++) sc[mt][nt][u] = 0.f;

        const uint32_t kb = smb + KS_OFF + buf + kbofs;
        #pragma unroll
        for (int kk = 0; kk < 8; kk++) {
            uint32_t a0[4], a1[4], b[4];
            LDSM_X4(a0, qa + kk * 32);
            LDSM_X4(a1, qa + kk * 32 + 16 * (SQH*2));
            LDSM_X4(b,  kb + kk * 32);
            MMA16816(sc[0][0], a0, b[0], b[1]);
            MMA16816(sc[0][1], a0, b[2], b[3]);
            MMA16816(sc[1][0], a1, b[0], b[1]);
            MMA16816(sc[1][1], a1, b[2], b[3]);
        }

        // ---- epilogue: mask + tanh-sigmoid ; stage P ; attn from regs ----
        #pragma unroll
        for (int mt = 0; mt < 2; mt++) {
            #pragma unroll
            for (int u = 0; u < 2; u++) {
                int rowl = wm*32 + mt*16 + gr + 8*u;      // local row
                size_t ar = (hseq + s0 + rowl) * SEQ + t0 + ecol0;
                unsigned m = mw[mt][u];
                #pragma unroll
                for (int nt = 0; nt < 2; nt++) {
                    int bitb = (wn & 1) * 16 + nt * 8 + 2 * ct;
                    // masked -> delta=0 -> tanh(0)=0 -> p=0.5 exactly
                    float x0 = ((m >> bitb) & 1)       ? 0.f : sc[mt][nt][2*u + 0];
                    float x1 = ((m >> (bitb + 1)) & 1) ? 0.f : sc[mt][nt][2*u + 1];
                    float p0 = sigp(x0);
                    float p1 = sigp(x1);
                    *(uint32_t*)(sm + PS_OFF + rowl * (SPH*2)
                                 + (wn*16 + nt*8 + 2*ct) * 2) = f22u(p0, p1);
                    __stcs((float2*)(attn  + ar + nt*8), make_float2(p0, p1));
                    __stcs((float2*)(attn1 + ar + nt*8),
                           make_float2(1.f - p0, 1.f - p1));
                }
            }
        }
        // per-m-half barrier: MMA2 of (wm,*) consumes P produced by (wm,*)
        BAR_SYNC(1 + wm);

        // ---- MMA2: O[64][128] += P0 * [V0|V1] ; warp tile 32x32 ----
        #pragma unroll
        for (int kk = 0; kk < 4; kk++) {
            uint32_t a0[4], a1[4], bA[4], bB[4];
            LDSM_X4(a0, pa + kk * 32);
            LDSM_X4(a1, pa + kk * 32 + 16 * (SPH*2));
            uint32_t vaddr = smb + VS_OFF + buf + vbrow + vbcol + (uint32_t)kk * 16 * (SQH*2);
            LDSM_X4T(bA, vaddr);
            LDSM_X4T(bB, vaddr + 32);
            MMA16816(oc[0][0], a0, bA[0], bA[1]);
            MMA16816(oc[0][1], a0, bA[2], bA[3]);
            MMA16816(oc[0][2], a0, bB[0], bB[1]);
            MMA16816(oc[0][3], a0, bB[2], bB[3]);
            MMA16816(oc[1][0], a1, bA[0], bA[1]);
            MMA16816(oc[1][1], a1, bA[2], bA[3]);
            MMA16816(oc[1][2], a1, bB[0], bB[1]);
            MMA16816(oc[1][3], a1, bB[2], bB[3]);
        }
    }

    // ---- final out write: wn 0,1 -> b0 = acc ; wn 2,3 -> b1 = v1sum - acc ----
    const float* vs = g_v1sum + h * HD;
    const int b = wn >> 1;
    #pragma unroll
    for (int mt = 0; mt < 2; mt++) {
        int row = s0 + wm*32 + mt*16 + gr;
        #pragma unroll
        for (int nt = 0; nt < 4; nt++) {
            int n0 = wn*32 + nt*8 + 2*ct;
            int d  = n0 & 63;
            float* c = oc[mt][nt];
            float2 w0, w1;
            if (b == 0) {
                w0 = make_float2(c[0], c[1]);
                w1 = make_float2(c[2], c[3]);
            } else {
                w0 = make_float2(vs[d] - c[0], vs[d + 1] - c[1]);
                w1 = make_float2(vs[d] - c[2], vs[d + 1] - c[3]);
            }
            size_t ob = (((size_t)b * NH + h) * SEQ + row) * HD + d;
            *(float2*)(out + ob)          = w0;
            *(float2*)(out + ob + 8 * HD) = w1;
        }
    }
}

// ---------------- launcher ----------------
extern "C" void kernel_launch(void* const* d_in, const int* in_sizes, int n_in,
                              void* d_out, int out_size)
{
    const float* q    = (const float*)d_in[0];
    const float* k    = (const float*)d_in[1];
    const float* v    = (const float*)d_in[2];
    const int*   mask = (const int*)  d_in[3];

    float* out  = (float*)d_out;
    float* attn = out + (size_t)2 * NH * SEQ * HD;

    prologue_kernel<<<3076, 256>>>(mask, k, v);

    cudaFuncSetAttribute(sdpa_mma_kernel,
                         cudaFuncAttributeMaxDynamicSharedMemorySize, SMEM_BYTES);
    dim3 grid(SEQ / BM, NH);
    sdpa_mma_kernel<<<grid, NTH, SMEM_BYTES>>>(q, out, attn);
}